// round 11
// baseline (speedup 1.0000x reference)
#include <cuda_runtime.h>
#include <cuda_fp16.h>
#include <cuda_bf16.h>
#include <cstdint>

// Problem constants
#define M_TOT   8192
#define K_TOT   4096
#define N_TOT   11008
#define MT64    128             // M tiles of 64
#define NT      86              // N tiles of 128
#define KC      64              // K chunks of 64 elems (packed block granularity)
#define KC2     32              // K stages of 128 elems (2 packed blocks)
#define TILE_BLK_BYTES 16384    // 128 rows * 128 bytes (64 fp16)

// Packed fp16 scratch (pre-swizzled tile blocks of 128 rows)
__device__ __align__(1024) unsigned char g_A[(size_t)M_TOT * K_TOT * 2];
__device__ __align__(1024) unsigned char g_W[(size_t)N_TOT * K_TOT * 2];

// Probe results
__device__ int g_sel;   // 0: cand0 is scale, 1: cand1 is scale
__device__ int g_dt;    // 0: f32, 1: f16, 2: bf16

// ---------------------------------------------------------------------------
// Helpers
// ---------------------------------------------------------------------------
__device__ __forceinline__ uint32_t h2u(__half2 h) {
    union { __half2 h; uint32_t u; } cvt; cvt.h = h; return cvt.u;
}
__device__ __forceinline__ uint32_t smem_u32(const void* p) {
    uint32_t a;
    asm("{ .reg .u64 t; cvta.to.shared.u64 t, %1; cvt.u32.u64 %0, t; }" : "=r"(a) : "l"(p));
    return a;
}
__device__ __forceinline__ uint32_t sw128(uint32_t off) {
    return off ^ ((off >> 3) & 0x70);
}
__device__ __forceinline__ void cp16(uint32_t dst, const void* src) {
    asm volatile("cp.async.cg.shared.global [%0], [%1], 16;" :: "r"(dst), "l"(src) : "memory");
}
__device__ __forceinline__ void cp_commit() {
    asm volatile("cp.async.commit_group;" ::: "memory");
}
template <int N>
__device__ __forceinline__ void cp_wait() {
    asm volatile("cp.async.wait_group %0;" :: "n"(N) : "memory");
}
// Non-volatile, "memory" clobber: cannot cross cp_wait/__syncthreads.
__device__ __forceinline__ void ldsm4(uint32_t& r0, uint32_t& r1, uint32_t& r2, uint32_t& r3,
                                      uint32_t addr) {
    asm("ldmatrix.sync.aligned.m8n8.x4.shared.b16 {%0,%1,%2,%3}, [%4];"
        : "=r"(r0), "=r"(r1), "=r"(r2), "=r"(r3) : "r"(addr) : "memory");
}
__device__ __forceinline__ void mma16816(float* c, const uint32_t* a, const uint32_t* b) {
    asm("mma.sync.aligned.m16n8k16.row.col.f32.f16.f16.f32 "
        "{%0,%1,%2,%3}, {%4,%5,%6,%7}, {%8,%9}, {%0,%1,%2,%3};"
        : "+f"(c[0]), "+f"(c[1]), "+f"(c[2]), "+f"(c[3])
        : "r"(a[0]), "r"(a[1]), "r"(a[2]), "r"(a[3]), "r"(b[0]), "r"(b[1]));
}
__device__ __forceinline__ float load_sb(const void* p, int i, int dt) {
    if (dt == 0) return ((const float*)p)[i];
    if (dt == 1) return __half2float(((const __half*)p)[i]);
    return __bfloat162float(((const __nv_bfloat16*)p)[i]);
}

// ---------------------------------------------------------------------------
// Probe: identify weight_scale array + dtype (scale in (5e-5, 0.02), positive).
// ---------------------------------------------------------------------------
__global__ void probe_kernel(const void* c0, const void* c1) {
    if (threadIdx.x != 0 || blockIdx.x != 0) return;
    const void* cands[2] = { c0, c1 };
    for (int dt = 0; dt < 3; dt++) {
        for (int s = 0; s < 2; s++) {
            bool ok = true;
            for (int i = 0; i < 32; i++) {
                float v = load_sb(cands[s], i, dt);
                if (!(v > 5e-5f && v < 0.02f)) { ok = false; break; }
            }
            if (ok) { g_sel = s; g_dt = dt; return; }
        }
    }
    g_sel = 0; g_dt = 1;
}

// ---------------------------------------------------------------------------
// Pack kernels: fp32/int32 -> fp16, tile-packed & pre-swizzled (128-row blocks)
// ---------------------------------------------------------------------------
__global__ void pack_a_kernel(const float* __restrict__ x) {
    size_t t = (size_t)blockIdx.x * blockDim.x + threadIdx.x;
    size_t g = t * 8;
    int m = (int)(g >> 12);
    int k = (int)(g & 4095);
    float4 f0 = *(const float4*)(x + g);
    float4 f1 = *(const float4*)(x + g + 4);
    uint4 pk;
    pk.x = h2u(__floats2half2_rn(f0.x, f0.y));
    pk.y = h2u(__floats2half2_rn(f0.z, f0.w));
    pk.z = h2u(__floats2half2_rn(f1.x, f1.y));
    pk.w = h2u(__floats2half2_rn(f1.z, f1.w));
    int mt = m >> 7, r = m & 127, kc = k >> 6, c = k & 63;
    uint32_t off = sw128((uint32_t)(r * 128 + c * 2));
    *(uint4*)(g_A + (size_t)(mt * KC + kc) * TILE_BLK_BYTES + off) = pk;
}

__global__ void pack_w_kernel(const int* __restrict__ wq,
                              const void* __restrict__ c0, const void* __restrict__ c1) {
    size_t t = (size_t)blockIdx.x * blockDim.x + threadIdx.x;
    size_t g = t * 8;
    int n = (int)(g >> 12);
    int k = (int)(g & 4095);
    int4 q0 = *(const int4*)(wq + g);
    int4 q1 = *(const int4*)(wq + g + 4);
    const void* sp = g_sel ? c1 : c0;
    float s = load_sb(sp, n, g_dt);
    uint4 pk;
    pk.x = h2u(__floats2half2_rn((float)q0.x * s, (float)q0.y * s));
    pk.y = h2u(__floats2half2_rn((float)q0.z * s, (float)q0.w * s));
    pk.z = h2u(__floats2half2_rn((float)q1.x * s, (float)q1.y * s));
    pk.w = h2u(__floats2half2_rn((float)q1.z * s, (float)q1.w * s));
    int nt = n >> 7, r = n & 127, kc = k >> 6, c = k & 63;
    uint32_t off = sw128((uint32_t)(r * 128 + c * 2));
    *(uint4*)(g_W + (size_t)(nt * KC + kc) * TILE_BLK_BYTES + off) = pk;
}

// ---------------------------------------------------------------------------
// GEMM: 64x128 CTA tile, 128 threads (4 warps, warp tile 32x64), K in 128-elem
// stages (8 MMA groups), 2 x 48KB smem stages -> 2 CTAs/SM for phase-
// decorrelated boundary covering. Fragment double buffer; last two MMA groups
// held across the barrier.
// Stage layout: [A k0 8KB | A k1 8KB | B k0 16KB | B k1 16KB]
// ---------------------------------------------------------------------------
#define STAGE_BYTES 49152       // 48KB
#define GEMM_SMEM   (2 * STAGE_BYTES)

__global__ void __launch_bounds__(128, 2)
gemm_kernel(float* __restrict__ out,
            const void* __restrict__ c0, const void* __restrict__ c1) {
    extern __shared__ char smem[];
    const uint32_t sb = smem_u32(smem);

    const int tid  = threadIdx.x;
    const int wid  = tid >> 5;
    const int lane = tid & 31;
    const int wm   = wid & 1;       // M offset 0/32
    const int wn   = wid >> 1;      // N offset wn*64
    const int mt   = blockIdx.x;    // 64-row M tile
    const int nt   = blockIdx.y;    // 128-col N tile

    // A: 64-row half of a 128-row packed block (swizzle commutes with +8192)
    const unsigned char* ablk = g_A + (size_t)((mt >> 1) * KC) * TILE_BLK_BYTES
                                     + (size_t)(mt & 1) * 8192;
    const unsigned char* bblk = g_W + (size_t)(nt * KC) * TILE_BLK_BYTES;

    // Copy one 48KB stage (K=128 = packed chunks 2*kc2, 2*kc2+1).
    // Per thread: A 2x4 + B 2x8 = 24 cp16.
    auto load_stage = [&](uint32_t sbase, int kc2) {
        uint32_t d = sbase + tid * 16;
        #pragma unroll
        for (int kb = 0; kb < 2; kb++) {
            size_t blk = (size_t)(2 * kc2 + kb) * TILE_BLK_BYTES;
            const unsigned char* sA = ablk + blk + tid * 16;
            const unsigned char* sB = bblk + blk + tid * 16;
            #pragma unroll
            for (int r = 0; r < 4; r++) cp16(d + kb * 8192 + r * 2048,          sA + r * 2048);
            #pragma unroll
            for (int r = 0; r < 8; r++) cp16(d + 16384 + kb * 16384 + r * 2048, sB + r * 2048);
        }
        cp_commit();
    };

    // Per-lane ldmatrix row/col patterns
    const int aj    = lane >> 3;
    const int arow  = wm * 32 + ((aj & 1) << 3) + (lane & 7);   // + i*16, rows 0..63
    const int acol  = (aj >> 1) << 3;                           // halves
    const int brow  = wn * 64 + ((lane >> 4) << 3) + (lane & 7); // + p*16, rows 0..127
    const int bcol  = ((lane >> 3) & 1) << 3;                   // halves

    float acc[2][8][4];
    #pragma unroll
    for (int i = 0; i < 2; i++)
        #pragma unroll
        for (int f = 0; f < 8; f++)
            #pragma unroll
            for (int c = 0; c < 4; c++) acc[i][f][c] = 0.f;

    // Fragment double buffers
    uint32_t afr[2][2][4];
    uint32_t bfr[2][8][2];

    // ks = 16-elem K group 0..7; groups 0..3 in chunk kb0, 4..7 in kb1.
    auto load_frags = [&](uint32_t sbase, int ks, int buf) {
        const uint32_t kboA = (ks & 4) ? 8192u : 0u;
        const uint32_t kboB = (ks & 4) ? 16384u : 0u;
        const int      kcol = (ks & 3) * 16;
        const uint32_t aBase = sbase + kboA;
        const uint32_t bBase = sbase + 16384 + kboB;
        #pragma unroll
        for (int i = 0; i < 2; i++) {
            uint32_t byte = (uint32_t)((arow + i * 16) * 128 + (acol + kcol) * 2);
            ldsm4(afr[buf][i][0], afr[buf][i][1], afr[buf][i][2], afr[buf][i][3],
                  aBase + sw128(byte));
        }
        #pragma unroll
        for (int p = 0; p < 4; p++) {
            uint32_t r0, r1, r2, r3;
            uint32_t byte = (uint32_t)((brow + p * 16) * 128 + (bcol + kcol) * 2);
            ldsm4(r0, r1, r2, r3, bBase + sw128(byte));
            bfr[buf][p * 2 + 0][0] = r0; bfr[buf][p * 2 + 0][1] = r1;
            bfr[buf][p * 2 + 1][0] = r2; bfr[buf][p * 2 + 1][1] = r3;
        }
    };

    auto mma_group = [&](int buf) {
        #pragma unroll
        for (int i = 0; i < 2; i++)
            #pragma unroll
            for (int f = 0; f < 8; f++)
                mma16816(acc[i][f], afr[buf][i], bfr[buf][f]);
    };

    // Prologue: stages 0, 1 in flight; wait stage 0; first frags.
    load_stage(sb, 0);
    load_stage(sb + STAGE_BYTES, 1);
    cp_wait<1>();
    __syncthreads();
    load_frags(sb, 0, 0);

    for (int kc2 = 0; kc2 < KC2; kc2++) {
        const uint32_t SS = sb + (uint32_t)(kc2 & 1) * STAGE_BYTES;

        // Groups 0..5 with rolling fragment double-buffer (loads ks1..ks6)
        #pragma unroll
        for (int ks = 0; ks < 6; ks++) {
            load_frags(SS, ks + 1, (ks + 1) & 1);
            mma_group(ks & 1);
        }
        // Load ks7 frags; ks6 (buf0) and ks7 (buf1) held across the barrier.
        load_frags(SS, 7, 1);

        if (kc2 + 1 < KC2) {
            cp_wait<0>();           // next stage landed (single pending group)
            __syncthreads();
            mma_group(0);           // held ks6: feeds tensor immediately
            if (kc2 + 2 < KC2) load_stage(SS, kc2 + 2);  // overwrite freed buffer
            mma_group(1);           // held ks7
            const uint32_t NS = sb + (uint32_t)((kc2 + 1) & 1) * STAGE_BYTES;
            load_frags(NS, 0, 0);   // next stage group 0
        } else {
            mma_group(0);
            mma_group(1);
        }
    }

    // ---- epilogue: add bias (dtype-probed), store float2 ----
    const void* bias = g_sel ? c0 : c1;
    const int dt = g_dt;
    const int col0 = nt * 128 + wn * 64 + (lane & 3) * 2;
    const int row0 = mt * 64 + wm * 32 + (lane >> 2);
    #pragma unroll
    for (int f = 0; f < 8; f++) {
        const int col = col0 + f * 8;
        const float b0 = load_sb(bias, col, dt);
        const float b1 = load_sb(bias, col + 1, dt);
        #pragma unroll
        for (int i = 0; i < 2; i++) {
            const int row = row0 + i * 16;
            float2 v0 = make_float2(acc[i][f][0] + b0, acc[i][f][1] + b1);
            float2 v1 = make_float2(acc[i][f][2] + b0, acc[i][f][3] + b1);
            *(float2*)(out + (size_t)row * N_TOT + col)       = v0;
            *(float2*)(out + (size_t)(row + 8) * N_TOT + col) = v1;
        }
    }
}

// ---------------------------------------------------------------------------
// Launch
// ---------------------------------------------------------------------------
extern "C" void kernel_launch(void* const* d_in, const int* in_sizes, int n_in,
                              void* d_out, int out_size) {
    const float* x  = nullptr;
    const int*   wq = nullptr;
    const void*  small[2] = { nullptr, nullptr };
    int nsmall = 0;
    for (int i = 0; i < n_in; i++) {
        long long sz = in_sizes[i];
        if (sz == (long long)M_TOT * K_TOT)      x  = (const float*)d_in[i];
        else if (sz == (long long)N_TOT * K_TOT) wq = (const int*)d_in[i];
        else if (sz == N_TOT && nsmall < 2)      small[nsmall++] = d_in[i];
    }
    float* out = (float*)d_out;

    cudaFuncSetAttribute(gemm_kernel, cudaFuncAttributeMaxDynamicSharedMemorySize, GEMM_SMEM);

    probe_kernel<<<1, 32>>>(small[0], small[1]);
    pack_a_kernel<<<(M_TOT * (size_t)K_TOT) / 8 / 256, 256>>>(x);
    pack_w_kernel<<<((size_t)N_TOT * K_TOT) / 8 / 256, 256>>>(wq, small[0], small[1]);

    dim3 grid(MT64, NT);
    gemm_kernel<<<grid, 128, GEMM_SMEM>>>(out, small[0], small[1]);
}

// round 14
// speedup vs baseline: 1.0092x; 1.0092x over previous
#include <cuda_runtime.h>
#include <cuda_fp16.h>
#include <cuda_bf16.h>
#include <cstdint>

// Problem constants
#define M_TOT   8192
#define K_TOT   4096
#define N_TOT   11008
#define MT      64              // M tiles of 128
#define NT2     43              // N tiles of 256
#define KC      64              // K chunks of 64 elems (packed block granularity)
#define KC2     32              // K stages of 128 elems (2 packed blocks)
#define TILE_BLK_BYTES 16384    // 128 rows * 128 bytes (64 fp16)

// Packed fp16 scratch (pre-swizzled tile blocks of 128 rows)
__device__ __align__(1024) unsigned char g_A[(size_t)M_TOT * K_TOT * 2];
__device__ __align__(1024) unsigned char g_W[(size_t)N_TOT * K_TOT * 2];

// Probe results
__device__ int g_sel;   // 0: cand0 is scale, 1: cand1 is scale
__device__ int g_dt;    // 0: f32, 1: f16, 2: bf16

// ---------------------------------------------------------------------------
// Helpers
// ---------------------------------------------------------------------------
__device__ __forceinline__ uint32_t h2u(__half2 h) {
    union { __half2 h; uint32_t u; } cvt; cvt.h = h; return cvt.u;
}
__device__ __forceinline__ uint32_t smem_u32(const void* p) {
    uint32_t a;
    asm("{ .reg .u64 t; cvta.to.shared.u64 t, %1; cvt.u32.u64 %0, t; }" : "=r"(a) : "l"(p));
    return a;
}
__device__ __forceinline__ uint32_t sw128(uint32_t off) {
    return off ^ ((off >> 3) & 0x70);
}
__device__ __forceinline__ void cp16(uint32_t dst, const void* src) {
    asm volatile("cp.async.cg.shared.global [%0], [%1], 16;" :: "r"(dst), "l"(src) : "memory");
}
__device__ __forceinline__ void cp_commit() {
    asm volatile("cp.async.commit_group;" ::: "memory");
}
template <int N>
__device__ __forceinline__ void cp_wait() {
    asm volatile("cp.async.wait_group %0;" :: "n"(N) : "memory");
}
// Non-volatile, "memory" clobber: cannot cross cp_wait/__syncthreads.
__device__ __forceinline__ void ldsm4(uint32_t& r0, uint32_t& r1, uint32_t& r2, uint32_t& r3,
                                      uint32_t addr) {
    asm("ldmatrix.sync.aligned.m8n8.x4.shared.b16 {%0,%1,%2,%3}, [%4];"
        : "=r"(r0), "=r"(r1), "=r"(r2), "=r"(r3) : "r"(addr) : "memory");
}
__device__ __forceinline__ void mma16816(float* c, const uint32_t* a, const uint32_t* b) {
    asm("mma.sync.aligned.m16n8k16.row.col.f32.f16.f16.f32 "
        "{%0,%1,%2,%3}, {%4,%5,%6,%7}, {%8,%9}, {%0,%1,%2,%3};"
        : "+f"(c[0]), "+f"(c[1]), "+f"(c[2]), "+f"(c[3])
        : "r"(a[0]), "r"(a[1]), "r"(a[2]), "r"(a[3]), "r"(b[0]), "r"(b[1]));
}
__device__ __forceinline__ float load_sb(const void* p, int i, int dt) {
    if (dt == 0) return ((const float*)p)[i];
    if (dt == 1) return __half2float(((const __half*)p)[i]);
    return __bfloat162float(((const __nv_bfloat16*)p)[i]);
}

// ---------------------------------------------------------------------------
// Probe: identify weight_scale array + dtype (scale in (5e-5, 0.02), positive).
// ---------------------------------------------------------------------------
__global__ void probe_kernel(const void* c0, const void* c1) {
    if (threadIdx.x != 0 || blockIdx.x != 0) return;
    const void* cands[2] = { c0, c1 };
    for (int dt = 0; dt < 3; dt++) {
        for (int s = 0; s < 2; s++) {
            bool ok = true;
            for (int i = 0; i < 32; i++) {
                float v = load_sb(cands[s], i, dt);
                if (!(v > 5e-5f && v < 0.02f)) { ok = false; break; }
            }
            if (ok) { g_sel = s; g_dt = dt; return; }
        }
    }
    g_sel = 0; g_dt = 1;
}

// ---------------------------------------------------------------------------
// Pack kernels: fp32/int32 -> fp16, tile-packed & pre-swizzled (128-row blocks)
// ---------------------------------------------------------------------------
__global__ void pack_a_kernel(const float* __restrict__ x) {
    size_t t = (size_t)blockIdx.x * blockDim.x + threadIdx.x;
    size_t g = t * 8;
    int m = (int)(g >> 12);
    int k = (int)(g & 4095);
    float4 f0 = *(const float4*)(x + g);
    float4 f1 = *(const float4*)(x + g + 4);
    uint4 pk;
    pk.x = h2u(__floats2half2_rn(f0.x, f0.y));
    pk.y = h2u(__floats2half2_rn(f0.z, f0.w));
    pk.z = h2u(__floats2half2_rn(f1.x, f1.y));
    pk.w = h2u(__floats2half2_rn(f1.z, f1.w));
    int mt = m >> 7, r = m & 127, kc = k >> 6, c = k & 63;
    uint32_t off = sw128((uint32_t)(r * 128 + c * 2));
    *(uint4*)(g_A + (size_t)(mt * KC + kc) * TILE_BLK_BYTES + off) = pk;
}

__global__ void pack_w_kernel(const int* __restrict__ wq,
                              const void* __restrict__ c0, const void* __restrict__ c1) {
    size_t t = (size_t)blockIdx.x * blockDim.x + threadIdx.x;
    size_t g = t * 8;
    int n = (int)(g >> 12);
    int k = (int)(g & 4095);
    int4 q0 = *(const int4*)(wq + g);
    int4 q1 = *(const int4*)(wq + g + 4);
    const void* sp = g_sel ? c1 : c0;
    float s = load_sb(sp, n, g_dt);
    uint4 pk;
    pk.x = h2u(__floats2half2_rn((float)q0.x * s, (float)q0.y * s));
    pk.y = h2u(__floats2half2_rn((float)q0.z * s, (float)q0.w * s));
    pk.z = h2u(__floats2half2_rn((float)q1.x * s, (float)q1.y * s));
    pk.w = h2u(__floats2half2_rn((float)q1.z * s, (float)q1.w * s));
    int nt = n >> 7, r = n & 127, kc = k >> 6, c = k & 63;
    uint32_t off = sw128((uint32_t)(r * 128 + c * 2));
    *(uint4*)(g_W + (size_t)(nt * KC + kc) * TILE_BLK_BYTES + off) = pk;
}

// ---------------------------------------------------------------------------
// GEMM: 128x256 CTA tile, K in 128-elem stages (8 MMA groups), 2 x 96KB smem
// stages. Copy for stage s+1 is issued as 3 x 8-cp16 chunks interleaved with
// MMA groups 0..2 of stage s (de-bursted). Last two MMA groups held across the
// barrier. 8 warps, warp tile 64x64.
// Stage layout: [A k0|A k1 | B0 k0|B0 k1 | B1 k0|B1 k1], 16KB blocks.
// ---------------------------------------------------------------------------
#define STAGE_BYTES 98304       // 6 x 16KB
#define GEMM_SMEM   (2 * STAGE_BYTES)

__global__ void __launch_bounds__(256, 1)
gemm_kernel(float* __restrict__ out,
            const void* __restrict__ c0, const void* __restrict__ c1) {
    extern __shared__ char smem[];
    const uint32_t sb = smem_u32(smem);

    const int tid  = threadIdx.x;
    const int wid  = tid >> 5;
    const int lane = tid & 31;
    const int wm   = wid & 1;       // M offset 0/64
    const int wn   = wid >> 1;      // N offset wn*64
    const int mt   = blockIdx.x;
    const int nt2  = blockIdx.y;

    const unsigned char* ablk  = g_A + (size_t)(mt * KC) * TILE_BLK_BYTES;
    const unsigned char* bblk0 = g_W + (size_t)((2 * nt2)     * KC) * TILE_BLK_BYTES;
    const unsigned char* bblk1 = g_W + (size_t)((2 * nt2 + 1) * KC) * TILE_BLK_BYTES;

    // Full 96KB stage copy (prologue only), with commit.
    auto load_stage = [&](uint32_t sbase, int kc2) {
        uint32_t d = sbase + tid * 16;
        #pragma unroll
        for (int kb = 0; kb < 2; kb++) {
            size_t blk = (size_t)(2 * kc2 + kb) * TILE_BLK_BYTES;
            const unsigned char* sA  = ablk  + blk + tid * 16;
            const unsigned char* sB0 = bblk0 + blk + tid * 16;
            const unsigned char* sB1 = bblk1 + blk + tid * 16;
            #pragma unroll
            for (int r = 0; r < 4; r++) cp16(d + kb * 16384 + r * 4096,         sA  + r * 4096);
            #pragma unroll
            for (int r = 0; r < 4; r++) cp16(d + 32768 + kb * 16384 + r * 4096, sB0 + r * 4096);
            #pragma unroll
            for (int r = 0; r < 4; r++) cp16(d + 65536 + kb * 16384 + r * 4096, sB1 + r * 4096);
        }
        cp_commit();
    };

    // One third of a stage copy: blocks 2c, 2c+1 of the 6 x 16KB stage.
    // 8 cp16/thread. No commit (caller commits after chunk 2).
    auto copy_chunk = [&](uint32_t dbase, int kc2s, int c) {
        #pragma unroll
        for (int jj = 0; jj < 2; jj++) {
            const int j = 2 * c + jj;
            size_t blk = (size_t)(2 * kc2s + (j & 1)) * TILE_BLK_BYTES;
            const unsigned char* base = (j < 2) ? ablk : (j < 4) ? bblk0 : bblk1;
            const unsigned char* src = base + blk + tid * 16;
            uint32_t d = dbase + (uint32_t)j * 16384u + tid * 16;
            #pragma unroll
            for (int r = 0; r < 4; r++) cp16(d + r * 4096, src + r * 4096);
        }
    };

    // Per-lane ldmatrix row/col patterns
    const int aj    = lane >> 3;
    const int arow  = wm * 64 + ((aj & 1) << 3) + (lane & 7);
    const int acol  = (aj >> 1) << 3;                     // halves
    const int brow  = wn * 64 + ((lane >> 4) << 3) + (lane & 7);
    const int browb = brow & 127;                          // row within 128-row B block
    const uint32_t boff_wn = (wn >= 2) ? 32768u : 0u;      // B0 vs B1
    const int bcol  = ((lane >> 3) & 1) << 3;              // halves

    float acc[4][8][4];
    #pragma unroll
    for (int i = 0; i < 4; i++)
        #pragma unroll
        for (int f = 0; f < 8; f++)
            #pragma unroll
            for (int c = 0; c < 4; c++) acc[i][f][c] = 0.f;

    // Fragment double buffers
    uint32_t afr[2][4][4];
    uint32_t bfr[2][8][2];

    // ks selects 16-elem K-group 0..7; groups 0..3 in block kb0, 4..7 in kb1.
    auto load_frags = [&](uint32_t sbase, int ks, int buf) {
        const uint32_t kbo  = (ks & 4) ? 16384u : 0u;
        const int      kcol = (ks & 3) * 16;
        const uint32_t aBase = sbase + kbo;
        const uint32_t bBase = sbase + 32768 + boff_wn + kbo;
        #pragma unroll
        for (int i = 0; i < 4; i++) {
            uint32_t byte = (uint32_t)((arow + i * 16) * 128 + (acol + kcol) * 2);
            ldsm4(afr[buf][i][0], afr[buf][i][1], afr[buf][i][2], afr[buf][i][3],
                  aBase + sw128(byte));
        }
        #pragma unroll
        for (int p = 0; p < 4; p++) {
            uint32_t r0, r1, r2, r3;
            uint32_t byte = (uint32_t)((browb + p * 16) * 128 + (bcol + kcol) * 2);
            ldsm4(r0, r1, r2, r3, bBase + sw128(byte));
            bfr[buf][p * 2 + 0][0] = r0; bfr[buf][p * 2 + 0][1] = r1;
            bfr[buf][p * 2 + 1][0] = r2; bfr[buf][p * 2 + 1][1] = r3;
        }
    };

    auto mma_group = [&](int buf) {
        #pragma unroll
        for (int i = 0; i < 4; i++)
            #pragma unroll
            for (int f = 0; f < 8; f++)
                mma16816(acc[i][f], afr[buf][i], bfr[buf][f]);
    };

    // Prologue: stage 0 burst; wait; first frags. (Stage 1 copied during stage 0.)
    load_stage(sb, 0);
    cp_wait<0>();
    __syncthreads();
    load_frags(sb, 0, 0);

    for (int kc2 = 0; kc2 < KC2; kc2++) {
        const uint32_t SS = sb + (uint32_t)(kc2 & 1) * STAGE_BYTES;
        const uint32_t DD = sb + (uint32_t)((kc2 + 1) & 1) * STAGE_BYTES;
        const bool do_copy = (kc2 + 1 < KC2);

        // Groups 0..5 with rolling fragment double-buffer; chunks of next
        // stage's copy interleaved with groups 0..2.
        #pragma unroll
        for (int ks = 0; ks < 6; ks++) {
            load_frags(SS, ks + 1, (ks + 1) & 1);
            if (ks < 3 && do_copy) {
                copy_chunk(DD, kc2 + 1, ks);
                if (ks == 2) cp_commit();
            }
            mma_group(ks & 1);
        }
        // Load ks7 frags; ks6 (buf0) and ks7 (buf1) held across the barrier.
        load_frags(SS, 7, 1);

        if (do_copy) {
            cp_wait<0>();           // stage kc2+1 landed (committed ~5 groups ago)
            __syncthreads();        // all warps done reading stage kc2's buffer
            mma_group(0);           // held ks6: feeds tensor immediately
            mma_group(1);           // held ks7
            load_frags(DD, 0, 0);   // next stage group 0
        } else {
            mma_group(0);
            mma_group(1);
        }
    }

    // ---- epilogue: add bias (dtype-probed), store float2 ----
    const void* bias = g_sel ? c0 : c1;
    const int dt = g_dt;
    const int col0 = nt2 * 256 + wn * 64 + (lane & 3) * 2;
    const int row0 = mt * 128 + wm * 64 + (lane >> 2);
    #pragma unroll
    for (int f = 0; f < 8; f++) {
        const int col = col0 + f * 8;
        const float b0 = load_sb(bias, col, dt);
        const float b1 = load_sb(bias, col + 1, dt);
        #pragma unroll
        for (int i = 0; i < 4; i++) {
            const int row = row0 + i * 16;
            float2 v0 = make_float2(acc[i][f][0] + b0, acc[i][f][1] + b1);
            float2 v1 = make_float2(acc[i][f][2] + b0, acc[i][f][3] + b1);
            *(float2*)(out + (size_t)row * N_TOT + col)       = v0;
            *(float2*)(out + (size_t)(row + 8) * N_TOT + col) = v1;
        }
    }
}

// ---------------------------------------------------------------------------
// Launch
// ---------------------------------------------------------------------------
extern "C" void kernel_launch(void* const* d_in, const int* in_sizes, int n_in,
                              void* d_out, int out_size) {
    const float* x  = nullptr;
    const int*   wq = nullptr;
    const void*  small[2] = { nullptr, nullptr };
    int nsmall = 0;
    for (int i = 0; i < n_in; i++) {
        long long sz = in_sizes[i];
        if (sz == (long long)M_TOT * K_TOT)      x  = (const float*)d_in[i];
        else if (sz == (long long)N_TOT * K_TOT) wq = (const int*)d_in[i];
        else if (sz == N_TOT && nsmall < 2)      small[nsmall++] = d_in[i];
    }
    float* out = (float*)d_out;

    cudaFuncSetAttribute(gemm_kernel, cudaFuncAttributeMaxDynamicSharedMemorySize, GEMM_SMEM);

    probe_kernel<<<1, 32>>>(small[0], small[1]);
    pack_a_kernel<<<(M_TOT * (size_t)K_TOT) / 8 / 256, 256>>>(x);
    pack_w_kernel<<<((size_t)N_TOT * K_TOT) / 8 / 256, 256>>>(wq, small[0], small[1]);

    dim3 grid(MT, NT2);
    gemm_kernel<<<grid, 256, GEMM_SMEM>>>(out, small[0], small[1]);
}

// round 15
// speedup vs baseline: 1.0289x; 1.0195x over previous
#include <cuda_runtime.h>
#include <cuda_fp16.h>
#include <cuda_bf16.h>
#include <cstdint>

// Problem constants
#define M_TOT   8192
#define K_TOT   4096
#define N_TOT   11008
#define MT      64              // M tiles of 128
#define NT2     43              // N tiles of 256
#define NTILES  2752            // 64 * 43
#define NSM     152             // GB300 SM count (persistent grid)
#define KC      64              // K chunks of 64 elems (packed block granularity)
#define KC2     32              // K stages of 128 elems per tile
#define TILE_BLK_BYTES 16384    // 128 rows * 128 bytes (64 fp16)

// Packed fp16 scratch (pre-swizzled tile blocks of 128 rows)
__device__ __align__(1024) unsigned char g_A[(size_t)M_TOT * K_TOT * 2];
__device__ __align__(1024) unsigned char g_W[(size_t)N_TOT * K_TOT * 2];

// Probe results
__device__ int g_sel;   // 0: cand0 is scale, 1: cand1 is scale
__device__ int g_dt;    // 0: f32, 1: f16, 2: bf16

// ---------------------------------------------------------------------------
// Helpers
// ---------------------------------------------------------------------------
__device__ __forceinline__ uint32_t h2u(__half2 h) {
    union { __half2 h; uint32_t u; } cvt; cvt.h = h; return cvt.u;
}
__device__ __forceinline__ uint32_t smem_u32(const void* p) {
    uint32_t a;
    asm("{ .reg .u64 t; cvta.to.shared.u64 t, %1; cvt.u32.u64 %0, t; }" : "=r"(a) : "l"(p));
    return a;
}
__device__ __forceinline__ uint32_t sw128(uint32_t off) {
    return off ^ ((off >> 3) & 0x70);
}
__device__ __forceinline__ void cp16(uint32_t dst, const void* src) {
    asm volatile("cp.async.cg.shared.global [%0], [%1], 16;" :: "r"(dst), "l"(src) : "memory");
}
__device__ __forceinline__ void cp_commit() {
    asm volatile("cp.async.commit_group;" ::: "memory");
}
template <int N>
__device__ __forceinline__ void cp_wait() {
    asm volatile("cp.async.wait_group %0;" :: "n"(N) : "memory");
}
// Non-volatile, "memory" clobber: cannot cross cp_wait/__syncthreads.
__device__ __forceinline__ void ldsm4(uint32_t& r0, uint32_t& r1, uint32_t& r2, uint32_t& r3,
                                      uint32_t addr) {
    asm("ldmatrix.sync.aligned.m8n8.x4.shared.b16 {%0,%1,%2,%3}, [%4];"
        : "=r"(r0), "=r"(r1), "=r"(r2), "=r"(r3) : "r"(addr) : "memory");
}
__device__ __forceinline__ void mma16816(float* c, const uint32_t* a, const uint32_t* b) {
    asm("mma.sync.aligned.m16n8k16.row.col.f32.f16.f16.f32 "
        "{%0,%1,%2,%3}, {%4,%5,%6,%7}, {%8,%9}, {%0,%1,%2,%3};"
        : "+f"(c[0]), "+f"(c[1]), "+f"(c[2]), "+f"(c[3])
        : "r"(a[0]), "r"(a[1]), "r"(a[2]), "r"(a[3]), "r"(b[0]), "r"(b[1]));
}
__device__ __forceinline__ float load_sb(const void* p, int i, int dt) {
    if (dt == 0) return ((const float*)p)[i];
    if (dt == 1) return __half2float(((const __half*)p)[i]);
    return __bfloat162float(((const __nv_bfloat16*)p)[i]);
}

// ---------------------------------------------------------------------------
// Probe: identify weight_scale array + dtype (scale in (5e-5, 0.02), positive).
// ---------------------------------------------------------------------------
__global__ void probe_kernel(const void* c0, const void* c1) {
    if (threadIdx.x != 0 || blockIdx.x != 0) return;
    const void* cands[2] = { c0, c1 };
    for (int dt = 0; dt < 3; dt++) {
        for (int s = 0; s < 2; s++) {
            bool ok = true;
            for (int i = 0; i < 32; i++) {
                float v = load_sb(cands[s], i, dt);
                if (!(v > 5e-5f && v < 0.02f)) { ok = false; break; }
            }
            if (ok) { g_sel = s; g_dt = dt; return; }
        }
    }
    g_sel = 0; g_dt = 1;
}

// ---------------------------------------------------------------------------
// Pack kernels: fp32/int32 -> fp16, tile-packed & pre-swizzled (128-row blocks)
// ---------------------------------------------------------------------------
__global__ void pack_a_kernel(const float* __restrict__ x) {
    size_t t = (size_t)blockIdx.x * blockDim.x + threadIdx.x;
    size_t g = t * 8;
    int m = (int)(g >> 12);
    int k = (int)(g & 4095);
    float4 f0 = *(const float4*)(x + g);
    float4 f1 = *(const float4*)(x + g + 4);
    uint4 pk;
    pk.x = h2u(__floats2half2_rn(f0.x, f0.y));
    pk.y = h2u(__floats2half2_rn(f0.z, f0.w));
    pk.z = h2u(__floats2half2_rn(f1.x, f1.y));
    pk.w = h2u(__floats2half2_rn(f1.z, f1.w));
    int mt = m >> 7, r = m & 127, kc = k >> 6, c = k & 63;
    uint32_t off = sw128((uint32_t)(r * 128 + c * 2));
    *(uint4*)(g_A + (size_t)(mt * KC + kc) * TILE_BLK_BYTES + off) = pk;
}

__global__ void pack_w_kernel(const int* __restrict__ wq,
                              const void* __restrict__ c0, const void* __restrict__ c1) {
    size_t t = (size_t)blockIdx.x * blockDim.x + threadIdx.x;
    size_t g = t * 8;
    int n = (int)(g >> 12);
    int k = (int)(g & 4095);
    int4 q0 = *(const int4*)(wq + g);
    int4 q1 = *(const int4*)(wq + g + 4);
    const void* sp = g_sel ? c1 : c0;
    float s = load_sb(sp, n, g_dt);
    uint4 pk;
    pk.x = h2u(__floats2half2_rn((float)q0.x * s, (float)q0.y * s));
    pk.y = h2u(__floats2half2_rn((float)q0.z * s, (float)q0.w * s));
    pk.z = h2u(__floats2half2_rn((float)q1.x * s, (float)q1.y * s));
    pk.w = h2u(__floats2half2_rn((float)q1.z * s, (float)q1.w * s));
    int nt = n >> 7, r = n & 127, kc = k >> 6, c = k & 63;
    uint32_t off = sw128((uint32_t)(r * 128 + c * 2));
    *(uint4*)(g_W + (size_t)(nt * KC + kc) * TILE_BLK_BYTES + off) = pk;
}

// ---------------------------------------------------------------------------
// GEMM: persistent CTAs (grid = NSM). Each CTA streams 18-19 tiles of 128x256.
// Per-tile K in 128-elem stages (8 MMA groups), 2 x 96KB smem stages; the
// stage counter runs ACROSS tiles so the cp.async pipeline never drains.
// Last two MMA groups held across the barrier; epilogue right after them.
// Stage layout: [A k0|A k1 | B0 k0|B0 k1 | B1 k0|B1 k1], 16KB blocks.
// ---------------------------------------------------------------------------
#define STAGE_BYTES 98304       // 6 x 16KB
#define GEMM_SMEM   (2 * STAGE_BYTES)

__global__ void __launch_bounds__(256, 1)
gemm_kernel(float* __restrict__ out,
            const void* __restrict__ c0, const void* __restrict__ c1) {
    extern __shared__ char smem[];
    const uint32_t sb = smem_u32(smem);

    const int tid  = threadIdx.x;
    const int wid  = tid >> 5;
    const int lane = tid & 31;
    const int wm   = wid & 1;       // M offset 0/64
    const int wn   = wid >> 1;      // N offset wn*64
    const int bid  = blockIdx.x;

    // Tiles for this CTA: gt = bid + NSM*i.  2752 = 152*18 + 16.
    const int ntiles  = (bid < (NTILES - NSM * (NTILES / NSM))) ? (NTILES / NSM + 1)
                                                                : (NTILES / NSM);
    const int nstages = ntiles << 5;

    // Copy one 96KB stage, sources derived from the global stage counter.
    auto load_stage = [&](uint32_t sbase, int sg) {
        const int tc  = sg >> 5;
        const int k2  = sg & 31;
        const int gt  = bid + NSM * tc;
        const int mtc = gt & 63;
        const int n2c = gt >> 6;
        const unsigned char* sA  = g_A + (size_t)(mtc * KC + 2 * k2) * TILE_BLK_BYTES + tid * 16;
        const unsigned char* sB0 = g_W + (size_t)((2 * n2c)     * KC + 2 * k2) * TILE_BLK_BYTES + tid * 16;
        const unsigned char* sB1 = g_W + (size_t)((2 * n2c + 1) * KC + 2 * k2) * TILE_BLK_BYTES + tid * 16;
        uint32_t d = sbase + tid * 16;
        #pragma unroll
        for (int kb = 0; kb < 2; kb++) {
            #pragma unroll
            for (int r = 0; r < 4; r++) cp16(d + kb * 16384 + r * 4096,         sA  + kb * TILE_BLK_BYTES + r * 4096);
            #pragma unroll
            for (int r = 0; r < 4; r++) cp16(d + 32768 + kb * 16384 + r * 4096, sB0 + kb * TILE_BLK_BYTES + r * 4096);
            #pragma unroll
            for (int r = 0; r < 4; r++) cp16(d + 65536 + kb * 16384 + r * 4096, sB1 + kb * TILE_BLK_BYTES + r * 4096);
        }
        cp_commit();
    };

    // Per-lane ldmatrix row/col patterns
    const int aj    = lane >> 3;
    const int arow  = wm * 64 + ((aj & 1) << 3) + (lane & 7);
    const int acol  = (aj >> 1) << 3;                     // halves
    const int brow  = wn * 64 + ((lane >> 4) << 3) + (lane & 7);
    const int browb = brow & 127;                          // row within 128-row B block
    const uint32_t boff_wn = (wn >= 2) ? 32768u : 0u;      // B0 vs B1
    const int bcol  = ((lane >> 3) & 1) << 3;              // halves

    float acc[4][8][4];
    #pragma unroll
    for (int i = 0; i < 4; i++)
        #pragma unroll
        for (int f = 0; f < 8; f++)
            #pragma unroll
            for (int c = 0; c < 4; c++) acc[i][f][c] = 0.f;

    // Fragment double buffers
    uint32_t afr[2][4][4];
    uint32_t bfr[2][8][2];

    auto load_frags = [&](uint32_t sbase, int ks, int buf) {
        const uint32_t kbo  = (ks & 4) ? 16384u : 0u;
        const int      kcol = (ks & 3) * 16;
        const uint32_t aBase = sbase + kbo;
        const uint32_t bBase = sbase + 32768 + boff_wn + kbo;
        #pragma unroll
        for (int i = 0; i < 4; i++) {
            uint32_t byte = (uint32_t)((arow + i * 16) * 128 + (acol + kcol) * 2);
            ldsm4(afr[buf][i][0], afr[buf][i][1], afr[buf][i][2], afr[buf][i][3],
                  aBase + sw128(byte));
        }
        #pragma unroll
        for (int p = 0; p < 4; p++) {
            uint32_t r0, r1, r2, r3;
            uint32_t byte = (uint32_t)((browb + p * 16) * 128 + (bcol + kcol) * 2);
            ldsm4(r0, r1, r2, r3, bBase + sw128(byte));
            bfr[buf][p * 2 + 0][0] = r0; bfr[buf][p * 2 + 0][1] = r1;
            bfr[buf][p * 2 + 1][0] = r2; bfr[buf][p * 2 + 1][1] = r3;
        }
    };

    auto mma_group = [&](int buf) {
        #pragma unroll
        for (int i = 0; i < 4; i++)
            #pragma unroll
            for (int f = 0; f < 8; f++)
                mma16816(acc[i][f], afr[buf][i], bfr[buf][f]);
    };

    // Epilogue for tile tc: add bias, store, re-zero acc.
    const void* bias = g_sel ? c0 : c1;
    auto epilogue = [&](int tc) {
        const int gt  = bid + NSM * tc;
        const int mtc = gt & 63;
        const int n2c = gt >> 6;
        const int dt = g_dt;
        const int col0 = n2c * 256 + wn * 64 + (lane & 3) * 2;
        const int row0 = mtc * 128 + wm * 64 + (lane >> 2);
        #pragma unroll
        for (int f = 0; f < 8; f++) {
            const int col = col0 + f * 8;
            const float b0 = load_sb(bias, col, dt);
            const float b1 = load_sb(bias, col + 1, dt);
            #pragma unroll
            for (int i = 0; i < 4; i++) {
                const int row = row0 + i * 16;
                float2 v0 = make_float2(acc[i][f][0] + b0, acc[i][f][1] + b1);
                float2 v1 = make_float2(acc[i][f][2] + b0, acc[i][f][3] + b1);
                *(float2*)(out + (size_t)row * N_TOT + col)       = v0;
                *(float2*)(out + (size_t)(row + 8) * N_TOT + col) = v1;
            }
        }
        #pragma unroll
        for (int i = 0; i < 4; i++)
            #pragma unroll
            for (int f = 0; f < 8; f++)
                #pragma unroll
                for (int c = 0; c < 4; c++) acc[i][f][c] = 0.f;
    };

    // Prologue: stages 0, 1 in flight; wait stage 0; first frags.
    load_stage(sb, 0);
    load_stage(sb + STAGE_BYTES, 1);
    cp_wait<1>();
    __syncthreads();
    load_frags(sb, 0, 0);

    for (int sg = 0; sg < nstages; sg++) {
        const uint32_t SS = sb + (uint32_t)(sg & 1) * STAGE_BYTES;

        // Groups 0..5 with rolling fragment double-buffer (loads ks1..ks6)
        #pragma unroll
        for (int ks = 0; ks < 6; ks++) {
            load_frags(SS, ks + 1, (ks + 1) & 1);
            mma_group(ks & 1);
        }
        // ks7 frags; ks6 (buf0) and ks7 (buf1) held across the barrier.
        load_frags(SS, 7, 1);

        if (sg + 1 < nstages) {
            cp_wait<0>();           // stage sg+1 landed (single pending group)
            __syncthreads();        // all warps done reading buffer (sg&1)
            mma_group(0);           // held ks6: feeds tensor immediately
            if (sg + 2 < nstages) load_stage(SS, sg + 2);   // may be next tile
            mma_group(1);           // held ks7
            if ((sg & 31) == 31) epilogue(sg >> 5);         // tile finished
            load_frags(sb + (uint32_t)((sg + 1) & 1) * STAGE_BYTES, 0, 0);
        } else {
            mma_group(0);
            mma_group(1);
            epilogue(sg >> 5);
        }
    }
}

// ---------------------------------------------------------------------------
// Launch
// ---------------------------------------------------------------------------
extern "C" void kernel_launch(void* const* d_in, const int* in_sizes, int n_in,
                              void* d_out, int out_size) {
    const float* x  = nullptr;
    const int*   wq = nullptr;
    const void*  small[2] = { nullptr, nullptr };
    int nsmall = 0;
    for (int i = 0; i < n_in; i++) {
        long long sz = in_sizes[i];
        if (sz == (long long)M_TOT * K_TOT)      x  = (const float*)d_in[i];
        else if (sz == (long long)N_TOT * K_TOT) wq = (const int*)d_in[i];
        else if (sz == N_TOT && nsmall < 2)      small[nsmall++] = d_in[i];
    }
    float* out = (float*)d_out;

    cudaFuncSetAttribute(gemm_kernel, cudaFuncAttributeMaxDynamicSharedMemorySize, GEMM_SMEM);

    probe_kernel<<<1, 32>>>(small[0], small[1]);
    pack_a_kernel<<<(M_TOT * (size_t)K_TOT) / 8 / 256, 256>>>(x);
    pack_w_kernel<<<((size_t)N_TOT * K_TOT) / 8 / 256, 256>>>(wq, small[0], small[1]);

    gemm_kernel<<<NSM, 256, GEMM_SMEM>>>(out, small[0], small[1]);
}

// round 16
// speedup vs baseline: 1.0471x; 1.0176x over previous
#include <cuda_runtime.h>
#include <cuda_fp16.h>
#include <cuda_bf16.h>
#include <cstdint>

// Problem constants
#define M_TOT   8192
#define K_TOT   4096
#define N_TOT   11008
#define NTILES  2752            // 64 * 43 tiles of 128x256
#define NFULL   2736            // 152 * 18 -> perfectly balanced full tiles
#define NSM     152             // GB300 SM count (persistent grid)
#define KC      64              // K chunks of 64 elems (packed block granularity)
#define TILE_BLK_BYTES 16384    // 128 rows * 128 bytes (64 fp16)
#define FULL_STAGES 576         // 18 tiles * 32 stages

// Packed fp16 scratch (pre-swizzled tile blocks of 128 rows)
__device__ __align__(1024) unsigned char g_A[(size_t)M_TOT * K_TOT * 2];
__device__ __align__(1024) unsigned char g_W[(size_t)N_TOT * K_TOT * 2];

// Probe results
__device__ int g_sel;   // 0: cand0 is scale, 1: cand1 is scale
__device__ int g_dt;    // 0: f32, 1: f16, 2: bf16

// ---------------------------------------------------------------------------
// Helpers
// ---------------------------------------------------------------------------
__device__ __forceinline__ uint32_t h2u(__half2 h) {
    union { __half2 h; uint32_t u; } cvt; cvt.h = h; return cvt.u;
}
__device__ __forceinline__ uint32_t smem_u32(const void* p) {
    uint32_t a;
    asm("{ .reg .u64 t; cvta.to.shared.u64 t, %1; cvt.u32.u64 %0, t; }" : "=r"(a) : "l"(p));
    return a;
}
__device__ __forceinline__ uint32_t sw128(uint32_t off) {
    return off ^ ((off >> 3) & 0x70);
}
__device__ __forceinline__ void cp16(uint32_t dst, const void* src) {
    asm volatile("cp.async.cg.shared.global [%0], [%1], 16;" :: "r"(dst), "l"(src) : "memory");
}
__device__ __forceinline__ void cp_commit() {
    asm volatile("cp.async.commit_group;" ::: "memory");
}
template <int N>
__device__ __forceinline__ void cp_wait() {
    asm volatile("cp.async.wait_group %0;" :: "n"(N) : "memory");
}
// Non-volatile, "memory" clobber: cannot cross cp_wait/__syncthreads.
__device__ __forceinline__ void ldsm4(uint32_t& r0, uint32_t& r1, uint32_t& r2, uint32_t& r3,
                                      uint32_t addr) {
    asm("ldmatrix.sync.aligned.m8n8.x4.shared.b16 {%0,%1,%2,%3}, [%4];"
        : "=r"(r0), "=r"(r1), "=r"(r2), "=r"(r3) : "r"(addr) : "memory");
}
__device__ __forceinline__ void mma16816(float* c, const uint32_t* a, const uint32_t* b) {
    asm("mma.sync.aligned.m16n8k16.row.col.f32.f16.f16.f32 "
        "{%0,%1,%2,%3}, {%4,%5,%6,%7}, {%8,%9}, {%0,%1,%2,%3};"
        : "+f"(c[0]), "+f"(c[1]), "+f"(c[2]), "+f"(c[3])
        : "r"(a[0]), "r"(a[1]), "r"(a[2]), "r"(a[3]), "r"(b[0]), "r"(b[1]));
}
__device__ __forceinline__ float load_sb(const void* p, int i, int dt) {
    if (dt == 0) return ((const float*)p)[i];
    if (dt == 1) return __half2float(((const __half*)p)[i]);
    return __bfloat162float(((const __nv_bfloat16*)p)[i]);
}

// ---------------------------------------------------------------------------
// Probe: identify weight_scale array + dtype (scale in (5e-5, 0.02), positive).
// ---------------------------------------------------------------------------
__global__ void probe_kernel(const void* c0, const void* c1) {
    if (threadIdx.x != 0 || blockIdx.x != 0) return;
    const void* cands[2] = { c0, c1 };
    for (int dt = 0; dt < 3; dt++) {
        for (int s = 0; s < 2; s++) {
            bool ok = true;
            for (int i = 0; i < 32; i++) {
                float v = load_sb(cands[s], i, dt);
                if (!(v > 5e-5f && v < 0.02f)) { ok = false; break; }
            }
            if (ok) { g_sel = s; g_dt = dt; return; }
        }
    }
    g_sel = 0; g_dt = 1;
}

// ---------------------------------------------------------------------------
// Zero-init the 16 remainder tiles' output regions (they receive atomicAdd).
// 16 tiles * 128 rows * 64 float4 = 131072 float4s.
// ---------------------------------------------------------------------------
__global__ void zero_tail_kernel(float* __restrict__ out) {
    int v = blockIdx.x * blockDim.x + threadIdx.x;      // 0..131071
    int t   = v >> 13;           // tile 0..15
    int rem = v & 8191;
    int row = rem >> 6;          // 0..127
    int c4  = rem & 63;          // 0..63 float4s
    int gt  = NFULL + t;
    int row_g = (gt & 63) * 128 + row;
    int col_g = (gt >> 6) * 256 + c4 * 4;
    *(float4*)(out + (size_t)row_g * N_TOT + col_g) = make_float4(0.f, 0.f, 0.f, 0.f);
}

// ---------------------------------------------------------------------------
// Pack kernels: fp32/int32 -> fp16, tile-packed & pre-swizzled (128-row blocks)
// ---------------------------------------------------------------------------
__global__ void pack_a_kernel(const float* __restrict__ x) {
    size_t t = (size_t)blockIdx.x * blockDim.x + threadIdx.x;
    size_t g = t * 8;
    int m = (int)(g >> 12);
    int k = (int)(g & 4095);
    float4 f0 = *(const float4*)(x + g);
    float4 f1 = *(const float4*)(x + g + 4);
    uint4 pk;
    pk.x = h2u(__floats2half2_rn(f0.x, f0.y));
    pk.y = h2u(__floats2half2_rn(f0.z, f0.w));
    pk.z = h2u(__floats2half2_rn(f1.x, f1.y));
    pk.w = h2u(__floats2half2_rn(f1.z, f1.w));
    int mt = m >> 7, r = m & 127, kc = k >> 6, c = k & 63;
    uint32_t off = sw128((uint32_t)(r * 128 + c * 2));
    *(uint4*)(g_A + (size_t)(mt * KC + kc) * TILE_BLK_BYTES + off) = pk;
}

__global__ void pack_w_kernel(const int* __restrict__ wq,
                              const void* __restrict__ c0, const void* __restrict__ c1) {
    size_t t = (size_t)blockIdx.x * blockDim.x + threadIdx.x;
    size_t g = t * 8;
    int n = (int)(g >> 12);
    int k = (int)(g & 4095);
    int4 q0 = *(const int4*)(wq + g);
    int4 q1 = *(const int4*)(wq + g + 4);
    const void* sp = g_sel ? c1 : c0;
    float s = load_sb(sp, n, g_dt);
    uint4 pk;
    pk.x = h2u(__floats2half2_rn((float)q0.x * s, (float)q0.y * s));
    pk.y = h2u(__floats2half2_rn((float)q0.z * s, (float)q0.w * s));
    pk.z = h2u(__floats2half2_rn((float)q1.x * s, (float)q1.y * s));
    pk.w = h2u(__floats2half2_rn((float)q1.z * s, (float)q1.w * s));
    int nt = n >> 7, r = n & 127, kc = k >> 6, c = k & 63;
    uint32_t off = sw128((uint32_t)(r * 128 + c * 2));
    *(uint4*)(g_W + (size_t)(nt * KC + kc) * TILE_BLK_BYTES + off) = pk;
}

// ---------------------------------------------------------------------------
// GEMM: persistent CTAs (grid = NSM). Every CTA streams exactly 18 full tiles
// (576 stages); CTAs 0..31 additionally process one HALF-K job (16 stages) of
// the 16 remainder tiles, accumulating via atomicAdd (2 contributors ->
// commutative -> deterministic). Stage counter runs across jobs so the
// cp.async pipeline never drains.
// Stage layout: [A k0|A k1 | B0 k0|B0 k1 | B1 k0|B1 k1], 16KB blocks.
// ---------------------------------------------------------------------------
#define STAGE_BYTES 98304       // 6 x 16KB
#define GEMM_SMEM   (2 * STAGE_BYTES)

__global__ void __launch_bounds__(256, 1)
gemm_kernel(float* __restrict__ out,
            const void* __restrict__ c0, const void* __restrict__ c1) {
    extern __shared__ char smem[];
    const uint32_t sb = smem_u32(smem);

    const int tid  = threadIdx.x;
    const int wid  = tid >> 5;
    const int lane = tid & 31;
    const int wm   = wid & 1;       // M offset 0/64
    const int wn   = wid >> 1;      // N offset wn*64
    const int bid  = blockIdx.x;

    const int nstages = FULL_STAGES + ((bid < 32) ? 16 : 0);

    // Copy one 96KB stage; (tile, k2) derived from global stage counter.
    auto load_stage = [&](uint32_t sbase, int sg) {
        int gt, k2;
        if (sg < FULL_STAGES) { gt = bid + NSM * (sg >> 5); k2 = sg & 31; }
        else                  { gt = NFULL + (bid >> 1); k2 = ((bid & 1) << 4) + (sg - FULL_STAGES); }
        const int mtc = gt & 63;
        const int n2c = gt >> 6;
        const unsigned char* sA  = g_A + (size_t)(mtc * KC + 2 * k2) * TILE_BLK_BYTES + tid * 16;
        const unsigned char* sB0 = g_W + (size_t)((2 * n2c)     * KC + 2 * k2) * TILE_BLK_BYTES + tid * 16;
        const unsigned char* sB1 = g_W + (size_t)((2 * n2c + 1) * KC + 2 * k2) * TILE_BLK_BYTES + tid * 16;
        uint32_t d = sbase + tid * 16;
        #pragma unroll
        for (int kb = 0; kb < 2; kb++) {
            #pragma unroll
            for (int r = 0; r < 4; r++) cp16(d + kb * 16384 + r * 4096,         sA  + kb * TILE_BLK_BYTES + r * 4096);
            #pragma unroll
            for (int r = 0; r < 4; r++) cp16(d + 32768 + kb * 16384 + r * 4096, sB0 + kb * TILE_BLK_BYTES + r * 4096);
            #pragma unroll
            for (int r = 0; r < 4; r++) cp16(d + 65536 + kb * 16384 + r * 4096, sB1 + kb * TILE_BLK_BYTES + r * 4096);
        }
        cp_commit();
    };

    // Per-lane ldmatrix row/col patterns
    const int aj    = lane >> 3;
    const int arow  = wm * 64 + ((aj & 1) << 3) + (lane & 7);
    const int acol  = (aj >> 1) << 3;                     // halves
    const int brow  = wn * 64 + ((lane >> 4) << 3) + (lane & 7);
    const int browb = brow & 127;                          // row within 128-row B block
    const uint32_t boff_wn = (wn >= 2) ? 32768u : 0u;      // B0 vs B1
    const int bcol  = ((lane >> 3) & 1) << 3;              // halves

    float acc[4][8][4];
    #pragma unroll
    for (int i = 0; i < 4; i++)
        #pragma unroll
        for (int f = 0; f < 8; f++)
            #pragma unroll
            for (int c = 0; c < 4; c++) acc[i][f][c] = 0.f;

    // Fragment double buffers
    uint32_t afr[2][4][4];
    uint32_t bfr[2][8][2];

    auto load_frags = [&](uint32_t sbase, int ks, int buf) {
        const uint32_t kbo  = (ks & 4) ? 16384u : 0u;
        const int      kcol = (ks & 3) * 16;
        const uint32_t aBase = sbase + kbo;
        const uint32_t bBase = sbase + 32768 + boff_wn + kbo;
        #pragma unroll
        for (int i = 0; i < 4; i++) {
            uint32_t byte = (uint32_t)((arow + i * 16) * 128 + (acol + kcol) * 2);
            ldsm4(afr[buf][i][0], afr[buf][i][1], afr[buf][i][2], afr[buf][i][3],
                  aBase + sw128(byte));
        }
        #pragma unroll
        for (int p = 0; p < 4; p++) {
            uint32_t r0, r1, r2, r3;
            uint32_t byte = (uint32_t)((browb + p * 16) * 128 + (bcol + kcol) * 2);
            ldsm4(r0, r1, r2, r3, bBase + sw128(byte));
            bfr[buf][p * 2 + 0][0] = r0; bfr[buf][p * 2 + 0][1] = r1;
            bfr[buf][p * 2 + 1][0] = r2; bfr[buf][p * 2 + 1][1] = r3;
        }
    };

    auto mma_group = [&](int buf) {
        #pragma unroll
        for (int i = 0; i < 4; i++)
            #pragma unroll
            for (int f = 0; f < 8; f++)
                mma16816(acc[i][f], afr[buf][i], bfr[buf][f]);
    };

    const void* bias = g_sel ? c0 : c1;

    // Full-tile epilogue: add bias, store, re-zero acc.
    auto epilogue = [&](int tc) {
        const int gt  = bid + NSM * tc;
        const int mtc = gt & 63;
        const int n2c = gt >> 6;
        const int dt = g_dt;
        const int col0 = n2c * 256 + wn * 64 + (lane & 3) * 2;
        const int row0 = mtc * 128 + wm * 64 + (lane >> 2);
        #pragma unroll
        for (int f = 0; f < 8; f++) {
            const int col = col0 + f * 8;
            const float b0 = load_sb(bias, col, dt);
            const float b1 = load_sb(bias, col + 1, dt);
            #pragma unroll
            for (int i = 0; i < 4; i++) {
                const int row = row0 + i * 16;
                float2 v0 = make_float2(acc[i][f][0] + b0, acc[i][f][1] + b1);
                float2 v1 = make_float2(acc[i][f][2] + b0, acc[i][f][3] + b1);
                *(float2*)(out + (size_t)row * N_TOT + col)       = v0;
                *(float2*)(out + (size_t)(row + 8) * N_TOT + col) = v1;
            }
        }
        #pragma unroll
        for (int i = 0; i < 4; i++)
            #pragma unroll
            for (int f = 0; f < 8; f++)
                #pragma unroll
                for (int c = 0; c < 4; c++) acc[i][f][c] = 0.f;
    };

    // Half-K epilogue: atomicAdd into zero-initialized region; bias folded
    // into the k-half-0 contribution. Exactly 2 commutative contributors ->
    // bitwise-deterministic result.
    auto epilogue_half = [&]() {
        const int gt  = NFULL + (bid >> 1);
        const int mtc = gt & 63;
        const int n2c = gt >> 6;
        const int dt = g_dt;
        const bool addb = (bid & 1) == 0;
        const int col0 = n2c * 256 + wn * 64 + (lane & 3) * 2;
        const int row0 = mtc * 128 + wm * 64 + (lane >> 2);
        #pragma unroll
        for (int f = 0; f < 8; f++) {
            const int col = col0 + f * 8;
            const float b0 = addb ? load_sb(bias, col, dt)     : 0.f;
            const float b1 = addb ? load_sb(bias, col + 1, dt) : 0.f;
            #pragma unroll
            for (int i = 0; i < 4; i++) {
                const int row = row0 + i * 16;
                atomicAdd(out + (size_t)row * N_TOT + col,           acc[i][f][0] + b0);
                atomicAdd(out + (size_t)row * N_TOT + col + 1,       acc[i][f][1] + b1);
                atomicAdd(out + (size_t)(row + 8) * N_TOT + col,     acc[i][f][2] + b0);
                atomicAdd(out + (size_t)(row + 8) * N_TOT + col + 1, acc[i][f][3] + b1);
            }
        }
    };

    // Prologue: stages 0, 1 in flight; wait stage 0; first frags.
    load_stage(sb, 0);
    load_stage(sb + STAGE_BYTES, 1);
    cp_wait<1>();
    __syncthreads();
    load_frags(sb, 0, 0);

    for (int sg = 0; sg < nstages; sg++) {
        const uint32_t SS = sb + (uint32_t)(sg & 1) * STAGE_BYTES;

        // Groups 0..5 with rolling fragment double-buffer (loads ks1..ks6)
        #pragma unroll
        for (int ks = 0; ks < 6; ks++) {
            load_frags(SS, ks + 1, (ks + 1) & 1);
            mma_group(ks & 1);
        }
        // ks7 frags; ks6 (buf0) and ks7 (buf1) held across the barrier.
        load_frags(SS, 7, 1);

        if (sg + 1 < nstages) {
            cp_wait<0>();           // stage sg+1 landed (single pending group)
            __syncthreads();        // all warps done reading buffer (sg&1)
            mma_group(0);           // held ks6: feeds tensor immediately
            if (sg + 2 < nstages) load_stage(SS, sg + 2);   // may be next job
            mma_group(1);           // held ks7
            if ((sg & 31) == 31 && sg < FULL_STAGES) epilogue(sg >> 5);
            load_frags(sb + (uint32_t)((sg + 1) & 1) * STAGE_BYTES, 0, 0);
        } else {
            mma_group(0);
            mma_group(1);
            if (sg < FULL_STAGES) epilogue(sg >> 5);
            else                  epilogue_half();
        }
    }
}

// ---------------------------------------------------------------------------
// Launch
// ---------------------------------------------------------------------------
extern "C" void kernel_launch(void* const* d_in, const int* in_sizes, int n_in,
                              void* d_out, int out_size) {
    const float* x  = nullptr;
    const int*   wq = nullptr;
    const void*  small[2] = { nullptr, nullptr };
    int nsmall = 0;
    for (int i = 0; i < n_in; i++) {
        long long sz = in_sizes[i];
        if (sz == (long long)M_TOT * K_TOT)      x  = (const float*)d_in[i];
        else if (sz == (long long)N_TOT * K_TOT) wq = (const int*)d_in[i];
        else if (sz == N_TOT && nsmall < 2)      small[nsmall++] = d_in[i];
    }
    float* out = (float*)d_out;

    cudaFuncSetAttribute(gemm_kernel, cudaFuncAttributeMaxDynamicSharedMemorySize, GEMM_SMEM);

    probe_kernel<<<1, 32>>>(small[0], small[1]);
    zero_tail_kernel<<<512, 256>>>(out);
    pack_a_kernel<<<(M_TOT * (size_t)K_TOT) / 8 / 256, 256>>>(x);
    pack_w_kernel<<<((size_t)N_TOT * K_TOT) / 8 / 256, 256>>>(wq, small[0], small[1]);

    gemm_kernel<<<NSM, 256, GEMM_SMEM>>>(out, small[0], small[1]);
}